// round 15
// baseline (speedup 1.0000x reference)
#include <cuda_runtime.h>
#include <cuda_fp16.h>

// kendallloss: 1 - 2 * [sum_{i>j} clip(p_i-p_j)*clip(t_i-t_j)] / (N*(N-1))
//
// 3-op inner loop (2x HADD2.SAT + HFMA2 per 2 pairs) via sat identity,
// analytic cross term, CHECKERBOARD orientation (validated rel_err 4.6e-5):
//   pd' = sat(u_i + v_j) = (clip(p_i-p_j)+1)/2,  u=h(0.5x), v=h(0.5-0.5x)
//   full_sum = 4*P - N^2
//
// R15 vs R14 (23.0us): overhead was per-tile, not in the loop. Persistent
// tile loop: grid 1036 = one full wave (7 blk/SM x 148), block g does tiles
// {g, g+1036, g+2072} (static round-robin, deterministic). Per-thread fp32
// accumulator across tiles -> ONE epilogue/reduction per block. Prefetch
// MOVs removed (measured neutral). Final partials: 2080 -> 1036.

#define TILE     256
#define RI       8
#define GRID_MAX 1036

__device__ double       g_part[GRID_MAX];
__device__ unsigned int g_done = 0;

__global__ __launch_bounds__(256, 7) void pair_kernel(const float* __restrict__ p,
                                                      const float* __restrict__ tg,
                                                      float* __restrict__ out,
                                                      int n, int ntiles) {
    const int t  = threadIdx.x;
    const int ig = t & 31;
    const int jg = t >> 5;
    const int s0 = jg * 16;

    __shared__ uint2 sjE[TILE / 2];
    __shared__ uint2 sjO[TILE / 2];

    float faP = 0.0f;

    for (int tile = blockIdx.x; tile < ntiles; tile += gridDim.x) {
        // Decode lower-triangle tile index: tile -> (bi, bj), bj <= bi.
        int r = (int)((sqrtf(8.0f * (float)tile + 1.0f) - 1.0f) * 0.5f);
        while ((r + 1) * (r + 2) / 2 <= tile) r++;
        while (r * (r + 1) / 2 > tile) r--;
        const int bi = r;
        const int bj = tile - r * (r + 1) / 2;
        const int ibase = bi * TILE;
        const int jbase = bj * TILE;

        __syncthreads();   // previous iteration's readers done before restage

        // Stage j-side, split by consuming i-parity:
        //   sjE[k] = { {v_p(j0), u_p(j1)}, {v_t(j0), u_t(j1)} }  (even i)
        //   sjO[k] = { {u_p(j0), v_p(j1)}, {u_t(j0), v_t(j1)} }  (odd  i)
        if (t < TILE / 2) {
            float2 pv2 = *(const float2*)(p  + jbase + 2 * t);
            float2 tv2 = *(const float2*)(tg + jbase + 2 * t);
            __half2 pE = __floats2half2_rn(0.5f - 0.5f * pv2.x, 0.5f * pv2.y);
            __half2 tE = __floats2half2_rn(0.5f - 0.5f * tv2.x, 0.5f * tv2.y);
            __half2 pO = __floats2half2_rn(0.5f * pv2.x, 0.5f - 0.5f * pv2.y);
            __half2 tO = __floats2half2_rn(0.5f * tv2.x, 0.5f - 0.5f * tv2.y);
            uint2 e, o;
            e.x = *(unsigned int*)&pE;  e.y = *(unsigned int*)&tE;
            o.x = *(unsigned int*)&pO;  o.y = *(unsigned int*)&tO;
            sjE[t] = e;
            sjO[t] = o;
        }

        // i-side: convert ONCE to half2 {u_i, v_i}; pass B lane-swaps.
        const int i0 = ibase + ig * RI;   // even base -> q parity == i parity
        __half2 apA[4], atA[4], apBs[4], atBs[4];
        {
            float4 pf0 = *(const float4*)(p  + i0);
            float4 pf1 = *(const float4*)(p  + i0 + 4);
            float4 tf0 = *(const float4*)(tg + i0);
            float4 tf1 = *(const float4*)(tg + i0 + 4);
            float pvx[RI] = {pf0.x, pf0.y, pf0.z, pf0.w, pf1.x, pf1.y, pf1.z, pf1.w};
            float tvx[RI] = {tf0.x, tf0.y, tf0.z, tf0.w, tf1.x, tf1.y, tf1.z, tf1.w};
#pragma unroll
            for (int h = 0; h < 4; h++) {
                int qe = 2 * h, qo = 2 * h + 1;
                apA[h]  = __floats2half2_rn(0.5f * pvx[qe], 0.5f - 0.5f * pvx[qe]);
                atA[h]  = __floats2half2_rn(0.5f * tvx[qe], 0.5f - 0.5f * tvx[qe]);
                apBs[h] = __floats2half2_rn(0.5f * pvx[qo], 0.5f - 0.5f * pvx[qo]);
                atBs[h] = __floats2half2_rn(0.5f * tvx[qo], 0.5f - 0.5f * tvx[qo]);
            }
        }
        __syncthreads();

        float tileSum = 0.0f;

        // ---- Pass A: even i, ap = {u_i, v_i}, reads sjE ----
        {
            __half2 acc[4];
#pragma unroll
            for (int h = 0; h < 4; h++) acc[h] = __float2half2_rn(0.0f);
#pragma unroll
            for (int s = 0; s < 16; s++) {
                uint2 v = sjE[s0 + s];           // warp-uniform LDS.64
                __half2 pj = *(__half2*)&v.x;
                __half2 tj = *(__half2*)&v.y;
#pragma unroll
                for (int h = 0; h < 4; h++) {
                    __half2 pd = __hadd2_sat(apA[h], pj);
                    __half2 td = __hadd2_sat(atA[h], tj);
                    acc[h] = __hfma2(pd, td, acc[h]);
                }
            }
#pragma unroll
            for (int h = 0; h < 4; h++) {
                float2 f = __half22float2(acc[h]);
                tileSum += f.x + f.y;
            }
        }

        // ---- Pass B: odd i, ap = {v_i, u_i} via lane swap, reads sjO ----
        {
            __half2 acc[4];
#pragma unroll
            for (int h = 0; h < 4; h++) acc[h] = __float2half2_rn(0.0f);
#pragma unroll
            for (int s = 0; s < 16; s++) {
                uint2 v = sjO[s0 + s];           // warp-uniform LDS.64
                __half2 pj = *(__half2*)&v.x;
                __half2 tj = *(__half2*)&v.y;
#pragma unroll
                for (int h = 0; h < 4; h++) {
                    __half2 pd = __hadd2_sat(__lowhigh2highlow(apBs[h]), pj);
                    __half2 td = __hadd2_sat(__lowhigh2highlow(atBs[h]), tj);
                    acc[h] = __hfma2(pd, td, acc[h]);
                }
            }
#pragma unroll
            for (int h = 0; h < 4; h++) {
                float2 f = __half22float2(acc[h]);
                tileSum += f.x + f.y;
            }
        }

        float wgt = (bi == bj) ? 1.0f : 2.0f;   // off-diag covers both orientations
        faP += wgt * tileSum;
    }

    // ---- ONE epilogue per block ----
#pragma unroll
    for (int off = 16; off; off >>= 1)
        faP += __shfl_down_sync(0xffffffffu, faP, off);
    __shared__ float wsum[8];
    if ((t & 31) == 0) wsum[t >> 5] = faP;
    __syncthreads();

    __shared__ int s_last;
    if (t == 0) {
        float bs = 0.0f;
#pragma unroll
        for (int w = 0; w < 8; w++) bs += wsum[w];
        g_part[blockIdx.x] = (double)bs;
        __threadfence();
        unsigned int done = atomicAdd(&g_done, 1u);
        s_last = (done == gridDim.x - 1);
    }
    __syncthreads();

    if (s_last) {
        // Last block: fixed-order double reduction over block partials.
        __shared__ double sd[256];
        double s = 0.0;
        for (int k = t; k < (int)gridDim.x; k += 256) s += g_part[k];
        sd[t] = s;
        __syncthreads();
        for (int off = 128; off; off >>= 1) {
            if (t < off) sd[t] += sd[t + off];
            __syncthreads();
        }
        if (t == 0) {
            double nn    = (double)n * (double)n;
            double denom = (double)n * (double)(n - 1);
            double full  = 4.0 * sd[0] - nn;      // full_sum = 4*P - N^2
            out[0] = (float)(1.0 - full / denom);
            g_done = 0;                           // reset for next graph replay
        }
    }
}

extern "C" void kernel_launch(void* const* d_in, const int* in_sizes, int n_in,
                              void* d_out, int out_size) {
    const float* p = (const float*)d_in[0];
    const float* t = (const float*)d_in[1];
    int n = in_sizes[0];              // 16384, divisible by TILE

    int T      = n / TILE;
    int ntiles = T * (T + 1) / 2;     // 2080 lower-triangle tiles
    int grid   = ntiles < GRID_MAX ? ntiles : GRID_MAX;   // one full wave
    pair_kernel<<<grid, 256>>>(p, t, (float*)d_out, n, ntiles);
}